// round 3
// baseline (speedup 1.0000x reference)
#include <cuda_runtime.h>
#include <math.h>

#define B 4
#define N 512
#define HID 100
#define HP 128
#define OUTF 6
#define IT 16            // receivers per K2 block

// Scratch (static device; no allocation anywhere)
__device__ float g_P[B * N * HP];
__device__ float g_Q[B * N * HP];
__device__ float g_sumQ[B * HP];
__device__ float g_colsum[B][6];

__device__ __forceinline__ unsigned long long add_f32x2(
    unsigned long long a, unsigned long long b)
{
    unsigned long long r;
    asm("add.rn.f32x2 %0, %1, %2;" : "=l"(r) : "l"(a), "l"(b));
    return r;
}

__device__ __forceinline__ float softplus_f(float v)
{
    return fmaxf(v, 0.f) + log1pf(expf(-fabsf(v)));
}

// ---------------------------------------------------------------------------
// K0: column sums of inp per batch: g_colsum[b][c] = sum_n inp[b][n][c]
// ---------------------------------------------------------------------------
__global__ __launch_bounds__(512) void k0_colsums(const float* __restrict__ inp)
{
    int b = blockIdx.x;
    int t = threadIdx.x;
    const float* e = inp + (b * N + t) * 6;
    float v[6];
    #pragma unroll
    for (int o = 0; o < 6; o++) v[o] = e[o];
    #pragma unroll
    for (int off = 16; off > 0; off >>= 1)
        #pragma unroll
        for (int o = 0; o < 6; o++)
            v[o] += __shfl_down_sync(0xFFFFFFFFu, v[o], off);
    __shared__ float sm[16][6];
    if ((t & 31) == 0)
        #pragma unroll
        for (int o = 0; o < 6; o++) sm[t >> 5][o] = v[o];
    __syncthreads();
    if (t < 6) {
        float s = 0.f;
        #pragma unroll
        for (int w = 0; w < 16; w++) s += sm[w][t];
        g_colsum[b][t] = s;
    }
}

// ---------------------------------------------------------------------------
// K1: build P', Q for all (b,n,k); fold sumQ in (linear in colsums).
// Block = 128 k-lanes handling 16 (b,n) rows; W1 loaded once per thread.
// ---------------------------------------------------------------------------
__global__ __launch_bounds__(128) void k1_build_PQ(
    const float* __restrict__ inp, const float* __restrict__ W1,
    const float* __restrict__ b1)
{
    int bn0 = blockIdx.x * 16;
    int k   = threadIdx.x;

    __shared__ float rows[16][6];
    if (threadIdx.x < 96) {
        int r = threadIdx.x / 6, c = threadIdx.x % 6;
        rows[r][c] = inp[(bn0 + r) * 6 + c];
    }
    __syncthreads();

    float w0=0,w1=0,w2=0,w3=0,w4=0,w5=0,w6=0,w7=0,w8=0,w9=0,bk=0;
    if (k < HID) {
        w0 = W1[0*HID+k]; w1 = W1[1*HID+k]; w2 = W1[2*HID+k]; w3 = W1[3*HID+k];
        w4 = W1[4*HID+k]; w5 = W1[5*HID+k]; w6 = W1[6*HID+k]; w7 = W1[7*HID+k];
        w8 = W1[8*HID+k]; w9 = W1[9*HID+k]; bk = b1[k];
    }

    #pragma unroll
    for (int r = 0; r < 16; r++) {
        float y = rows[r][0], x = rows[r][1], tau = rows[r][2];
        float sig = rows[r][3], c = rows[r][4], d = rows[r][5];
        float P = 0.f, Q = 0.f;
        if (k < HID) {
            P = tau*w0 + sig*w1 + c*w2 + d*w3 + y*w8 + x*w9 + bk;
            Q = tau*w4 + sig*w5 + c*w6 + d*w7 - y*w8 - x*w9;
        }
        g_P[(bn0 + r) * HP + k] = P;
        g_Q[(bn0 + r) * HP + k] = Q;
    }

    // one block per batch (n==0 tile) also writes sumQ from colsums
    if ((blockIdx.x & 31) == 0) {
        int b = blockIdx.x >> 5;
        float sq = 0.f;
        if (k < HID) {
            float cy = g_colsum[b][0], cx = g_colsum[b][1];
            float ct = g_colsum[b][2], cs = g_colsum[b][3];
            float cc = g_colsum[b][4], cd = g_colsum[b][5];
            sq = ct*w4 + cs*w5 + cc*w6 + cd*w7 - cy*w8 - cx*w9;
        }
        g_sumQ[b * HP + k] = sq;
    }
}

// ---------------------------------------------------------------------------
// K2: fused O(N^2) abs-sum + epilogue.
// Block = 256 thr = 4 j-groups x 64 packed k-lanes; IT=16 receivers.
// Inner: t2 = p2+q2 (FADD2, fma pipe); abs via sign-mask (LOP3, alu pipe);
//        acc2 += t2 (FADD2). Pipes balanced -> issue-limited at 1/cyc.
// ---------------------------------------------------------------------------
__global__ __launch_bounds__(256) void k2_fused(
    const float* __restrict__ inp, const float* __restrict__ W2,
    const float* __restrict__ b2, float* __restrict__ out)
{
    int b    = blockIdx.x >> 5;              // 32 tiles per batch
    int i0   = (blockIdx.x & 31) * IT;
    int tid  = threadIdx.x;
    int jg   = tid >> 6;                     // 0..3
    int lane = tid & 63;                     // packed k-pair

    const unsigned long long* P2 =
        (const unsigned long long*)(g_P + (b * N + i0) * HP) + lane;
    unsigned long long p2[IT];
    #pragma unroll
    for (int ii = 0; ii < IT; ii++) p2[ii] = P2[ii * (HP / 2)];

    unsigned long long acc[IT];
    #pragma unroll
    for (int ii = 0; ii < IT; ii++) acc[ii] = 0ULL;

    const unsigned long long* Q2 =
        (const unsigned long long*)(g_Q + (b * N + jg * (N / 4)) * HP) + lane;
    #pragma unroll 4
    for (int j = 0; j < N / 4; j++) {
        unsigned long long q2 = Q2[j * (HP / 2)];
        #pragma unroll
        for (int ii = 0; ii < IT; ii++) {
            unsigned long long t = add_f32x2(p2[ii], q2);
            t &= 0x7FFFFFFF7FFFFFFFULL;          // packed fabs (2x LOP3, alu pipe)
            acc[ii] = add_f32x2(acc[ii], t);
        }
    }

    // stage partials: smT[jgroup][i][k], rows padded to keep 8B alignment
    __shared__ float smT[4][IT][HP + 4];
    #pragma unroll
    for (int ii = 0; ii < IT; ii++)
        *(unsigned long long*)&smT[jg][ii][2 * lane] = acc[ii];
    __syncthreads();

    // epilogue: thread -> (i = tid>>4, sub = tid&15), sub owns k = sub*8..+7
    int i   = tid >> 4;
    int sub = tid & 15;
    int gi  = b * N + i0 + i;

    float par[OUTF];
    #pragma unroll
    for (int o = 0; o < OUTF; o++) par[o] = 0.f;

    if (sub * 8 < HID) {
        #pragma unroll
        for (int kk = 0; kk < 8; kk++) {
            int k = sub * 8 + kk;
            if (k < HID) {
                float T = (smT[0][i][k] + smT[1][i][k])
                        + (smT[2][i][k] + smT[3][i][k]);
                float Pi = g_P[gi * HP + k];
                float Qi = g_Q[gi * HP + k];
                float sq = g_sumQ[b * HP + k];
                float S = 0.55f * ((float)(N - 1) * Pi + sq - Qi)
                        + 0.45f * (T - fabsf(Pi + Qi));
                #pragma unroll
                for (int o = 0; o < OUTF; o++)
                    par[o] += S * W2[k * OUTF + o];
            }
        }
    }
    #pragma unroll
    for (int off = 8; off > 0; off >>= 1)
        #pragma unroll
        for (int o = 0; o < OUTF; o++)
            par[o] += __shfl_down_sync(0xFFFFFFFFu, par[o], off, 16);

    if (sub == 0) {
        const float* e = inp + gi * 6;
        float* ot = out + gi * 6;
        float p0 = par[0] + (float)(N - 1) * b2[0];
        float p1 = par[1] + (float)(N - 1) * b2[1];
        float p2e = par[2] + (float)(N - 1) * b2[2];
        float p3 = par[3] + (float)(N - 1) * b2[3];
        float p4 = par[4] + (float)(N - 1) * b2[4];
        float p5 = par[5] + (float)(N - 1) * b2[5];
        ot[0] = e[0] + 0.1f * p0;
        ot[1] = e[1] + 0.1f * p1;
        ot[2] = e[2] + 0.1f * p2e;
        ot[3] = e[3] + 0.1f * p3;
        ot[4] = 0.1f * softplus_f(p4);
        ot[5] = 0.1f * softplus_f(p5);
    }
}

// ---------------------------------------------------------------------------
extern "C" void kernel_launch(void* const* d_in, const int* in_sizes, int n_in,
                              void* d_out, int out_size)
{
    const float* inp = (const float*)d_in[0];
    const float* W1  = (const float*)d_in[1];
    const float* b1  = (const float*)d_in[2];
    const float* W2  = (const float*)d_in[3];
    const float* b2  = (const float*)d_in[4];
    float* out = (float*)d_out;

    k0_colsums<<<B, 512>>>(inp);
    k1_build_PQ<<<B * N / 16, 128>>>(inp, W1, b1);
    k2_fused<<<B * (N / IT), 256>>>(inp, W2, b2, out);
}

// round 4
// speedup vs baseline: 1.2371x; 1.2371x over previous
#include <cuda_runtime.h>
#include <math.h>

#define B 4
#define N 512
#define HID 100
#define HP 128
#define OUTF 6
#define IT 16            // receivers per K2 block
#define JG 4             // j-groups per block

// Scratch (static device; no allocation anywhere)
__device__ float g_P[B * N * HP];
__device__ float g_Q[B * N * HP];

__device__ __forceinline__ float softplus_f(float v)
{
    return fmaxf(v, 0.f) + log1pf(expf(-fabsf(v)));
}

// ---------------------------------------------------------------------------
// K1: build P', Q for all (b,n,k).  Block = 128 k-lanes x 16 (b,n) rows.
// ---------------------------------------------------------------------------
__global__ __launch_bounds__(128) void k1_build_PQ(
    const float* __restrict__ inp, const float* __restrict__ W1,
    const float* __restrict__ b1)
{
    int bn0 = blockIdx.x * 16;
    int k   = threadIdx.x;

    __shared__ float rows[16][6];
    if (threadIdx.x < 96) {
        int r = threadIdx.x / 6, c = threadIdx.x % 6;
        rows[r][c] = inp[(bn0 + r) * 6 + c];
    }
    __syncthreads();

    float w0=0,w1=0,w2=0,w3=0,w4=0,w5=0,w6=0,w7=0,w8=0,w9=0,bk=0;
    if (k < HID) {
        w0 = W1[0*HID+k]; w1 = W1[1*HID+k]; w2 = W1[2*HID+k]; w3 = W1[3*HID+k];
        w4 = W1[4*HID+k]; w5 = W1[5*HID+k]; w6 = W1[6*HID+k]; w7 = W1[7*HID+k];
        w8 = W1[8*HID+k]; w9 = W1[9*HID+k]; bk = b1[k];
    }

    #pragma unroll
    for (int r = 0; r < 16; r++) {
        float y = rows[r][0], x = rows[r][1], tau = rows[r][2];
        float sig = rows[r][3], c = rows[r][4], d = rows[r][5];
        float P = 0.f, Q = 0.f;
        if (k < HID) {
            P = tau*w0 + sig*w1 + c*w2 + d*w3 + y*w8 + x*w9 + bk;
            Q = tau*w4 + sig*w5 + c*w6 + d*w7 - y*w8 - x*w9;
        }
        g_P[(bn0 + r) * HP + k] = P;
        g_Q[(bn0 + r) * HP + k] = Q;
    }
}

// ---------------------------------------------------------------------------
// K2: fused O(N^2) abs-sum + sumQ + epilogue.
// Block = 512 thr = 4 j-groups x 128 k-lanes; IT=16 receivers; grid=128.
// Inner per (j,k): qv load; sq += qv; 16x { acc += |p+qv| }  (pure FADD,
// abs folded as source modifier).
// ---------------------------------------------------------------------------
__global__ __launch_bounds__(512) void k2_fused(
    const float* __restrict__ inp, const float* __restrict__ W2,
    const float* __restrict__ b2, float* __restrict__ out)
{
    int b   = blockIdx.x >> 5;               // 32 tiles per batch
    int i0  = (blockIdx.x & 31) * IT;
    int tid = threadIdx.x;
    int jg  = tid >> 7;                      // 0..3
    int k   = tid & (HP - 1);                // 0..127

    const float* Pp = g_P + (b * N + i0) * HP + k;
    float p[IT];
    #pragma unroll
    for (int ii = 0; ii < IT; ii++) p[ii] = Pp[ii * HP];

    float acc[IT];
    #pragma unroll
    for (int ii = 0; ii < IT; ii++) acc[ii] = 0.f;
    float sq = 0.f;

    const float* q = g_Q + (b * N + jg * (N / JG)) * HP + k;
    #pragma unroll 4
    for (int j = 0; j < N / JG; j++) {
        float qv = q[j * HP];
        sq += qv;
        #pragma unroll
        for (int ii = 0; ii < IT; ii++)
            acc[ii] += fabsf(p[ii] + qv);
    }

    __shared__ float smT[JG][IT][HP];
    __shared__ float smSQ[JG][HP];
    #pragma unroll
    for (int ii = 0; ii < IT; ii++) smT[jg][ii][k] = acc[ii];
    smSQ[jg][k] = sq;
    __syncthreads();

    // epilogue: warp w handles receiver i=w; lane sub owns k = sub + 32*kk
    int i   = tid >> 5;                      // 0..15
    int sub = tid & 31;
    int gi  = b * N + i0 + i;

    float par[OUTF];
    #pragma unroll
    for (int o = 0; o < OUTF; o++) par[o] = 0.f;

    #pragma unroll
    for (int kk = 0; kk < 4; kk++) {
        int kc = sub + 32 * kk;
        if (kc < HID) {
            float T = (smT[0][i][kc] + smT[1][i][kc])
                    + (smT[2][i][kc] + smT[3][i][kc]);
            float sqt = (smSQ[0][kc] + smSQ[1][kc])
                      + (smSQ[2][kc] + smSQ[3][kc]);
            float Pi = g_P[gi * HP + kc];
            float Qi = g_Q[gi * HP + kc];
            float S = 0.55f * ((float)(N - 1) * Pi + sqt - Qi)
                    + 0.45f * (T - fabsf(Pi + Qi));
            #pragma unroll
            for (int o = 0; o < OUTF; o++)
                par[o] += S * W2[kc * OUTF + o];
        }
    }
    #pragma unroll
    for (int off = 16; off > 0; off >>= 1)
        #pragma unroll
        for (int o = 0; o < OUTF; o++)
            par[o] += __shfl_down_sync(0xFFFFFFFFu, par[o], off);

    if (sub == 0) {
        const float* e = inp + gi * 6;
        float* ot = out + gi * 6;
        float p0 = par[0] + (float)(N - 1) * b2[0];
        float p1 = par[1] + (float)(N - 1) * b2[1];
        float p2 = par[2] + (float)(N - 1) * b2[2];
        float p3 = par[3] + (float)(N - 1) * b2[3];
        float p4 = par[4] + (float)(N - 1) * b2[4];
        float p5 = par[5] + (float)(N - 1) * b2[5];
        ot[0] = e[0] + 0.1f * p0;
        ot[1] = e[1] + 0.1f * p1;
        ot[2] = e[2] + 0.1f * p2;
        ot[3] = e[3] + 0.1f * p3;
        ot[4] = 0.1f * softplus_f(p4);
        ot[5] = 0.1f * softplus_f(p5);
    }
}

// ---------------------------------------------------------------------------
extern "C" void kernel_launch(void* const* d_in, const int* in_sizes, int n_in,
                              void* d_out, int out_size)
{
    const float* inp = (const float*)d_in[0];
    const float* W1  = (const float*)d_in[1];
    const float* b1  = (const float*)d_in[2];
    const float* W2  = (const float*)d_in[3];
    const float* b2  = (const float*)d_in[4];
    float* out = (float*)d_out;

    k1_build_PQ<<<B * N / 16, 128>>>(inp, W1, b1);
    k2_fused<<<B * (N / IT), 512>>>(inp, W2, b2, out);
}

// round 5
// speedup vs baseline: 2.6507x; 2.1426x over previous
#include <cuda_runtime.h>
#include <math.h>

#define B 4
#define N 512
#define HID 100
#define HP 128
#define OUTF 6
#define IT 16            // receivers per K2 block
#define JG 4             // j-groups per block
#define UJ 8             // j prefetch depth

// Scratch (static device; no allocation anywhere)
__device__ float g_P[B * N * HP];
__device__ float g_Q[B * N * HP];

__device__ __forceinline__ float softplus_f(float v)
{
    return fmaxf(v, 0.f) + log1pf(expf(-fabsf(v)));
}

// t = qv*1.0 + p  as FFMA with immediate multiplier (rt_SMSP=1 vs FADD's 2)
__device__ __forceinline__ float fma1(float q, float p)
{
    float r;
    asm("fma.rn.f32 %0, %1, 0f3F800000, %2;" : "=f"(r) : "f"(q), "f"(p));
    return r;
}

// ---------------------------------------------------------------------------
// K1: build P', Q for all (b,n,k).  Block = 128 k-lanes x 16 (b,n) rows.
// ---------------------------------------------------------------------------
__global__ __launch_bounds__(128) void k1_build_PQ(
    const float* __restrict__ inp, const float* __restrict__ W1,
    const float* __restrict__ b1)
{
    int bn0 = blockIdx.x * 16;
    int k   = threadIdx.x;

    __shared__ float rows[16][6];
    if (threadIdx.x < 96) {
        int r = threadIdx.x / 6, c = threadIdx.x % 6;
        rows[r][c] = inp[(bn0 + r) * 6 + c];
    }
    __syncthreads();

    float w0=0,w1=0,w2=0,w3=0,w4=0,w5=0,w6=0,w7=0,w8=0,w9=0,bk=0;
    if (k < HID) {
        w0 = W1[0*HID+k]; w1 = W1[1*HID+k]; w2 = W1[2*HID+k]; w3 = W1[3*HID+k];
        w4 = W1[4*HID+k]; w5 = W1[5*HID+k]; w6 = W1[6*HID+k]; w7 = W1[7*HID+k];
        w8 = W1[8*HID+k]; w9 = W1[9*HID+k]; bk = b1[k];
    }

    #pragma unroll
    for (int r = 0; r < 16; r++) {
        float y = rows[r][0], x = rows[r][1], tau = rows[r][2];
        float sig = rows[r][3], c = rows[r][4], d = rows[r][5];
        float P = 0.f, Q = 0.f;
        if (k < HID) {
            P = tau*w0 + sig*w1 + c*w2 + d*w3 + y*w8 + x*w9 + bk;
            Q = tau*w4 + sig*w5 + c*w6 + d*w7 - y*w8 - x*w9;
        }
        g_P[(bn0 + r) * HP + k] = P;
        g_Q[(bn0 + r) * HP + k] = Q;
    }
}

// ---------------------------------------------------------------------------
// K2: fused O(N^2) abs-sum + sumQ + epilogue.
// Block = 512 thr = 4 j-groups x 128 k-lanes; IT=16 receivers; grid=128.
// Inner per (j,k): qv (prefetched, MLP=8); sq += qv;
//   16x { t = FFMA-imm(qv,1,p)  [rt=1];  acc += |t|  [FADD rt=2] }
// ---------------------------------------------------------------------------
__global__ __launch_bounds__(512) void k2_fused(
    const float* __restrict__ inp, const float* __restrict__ W2,
    const float* __restrict__ b2, float* __restrict__ out)
{
    int b   = blockIdx.x >> 5;               // 32 tiles per batch
    int i0  = (blockIdx.x & 31) * IT;
    int tid = threadIdx.x;
    int jg  = tid >> 7;                      // 0..3
    int k   = tid & (HP - 1);                // 0..127

    const float* Pp = g_P + (b * N + i0) * HP + k;
    float p[IT];
    #pragma unroll
    for (int ii = 0; ii < IT; ii++) p[ii] = Pp[ii * HP];

    float acc[IT];
    #pragma unroll
    for (int ii = 0; ii < IT; ii++) acc[ii] = 0.f;
    float sq = 0.f;

    const float* q = g_Q + (b * N + jg * (N / JG)) * HP + k;
    for (int j0 = 0; j0 < N / JG; j0 += UJ) {
        float qb[UJ];
        #pragma unroll
        for (int u = 0; u < UJ; u++)          // batched loads -> MLP=8
            qb[u] = q[(j0 + u) * HP];
        #pragma unroll
        for (int u = 0; u < UJ; u++) {
            float qv = qb[u];
            sq += qv;
            #pragma unroll
            for (int ii = 0; ii < IT; ii++)
                acc[ii] += fabsf(fma1(qv, p[ii]));
        }
    }

    __shared__ float smT[JG][IT][HP];
    __shared__ float smSQ[JG][HP];
    #pragma unroll
    for (int ii = 0; ii < IT; ii++) smT[jg][ii][k] = acc[ii];
    smSQ[jg][k] = sq;
    __syncthreads();

    // epilogue: warp w handles receiver i=w; lane sub owns k = sub + 32*kk
    int i   = tid >> 5;                      // 0..15
    int sub = tid & 31;
    int gi  = b * N + i0 + i;

    float par[OUTF];
    #pragma unroll
    for (int o = 0; o < OUTF; o++) par[o] = 0.f;

    #pragma unroll
    for (int kk = 0; kk < 4; kk++) {
        int kc = sub + 32 * kk;
        if (kc < HID) {
            float T = (smT[0][i][kc] + smT[1][i][kc])
                    + (smT[2][i][kc] + smT[3][i][kc]);
            float sqt = (smSQ[0][kc] + smSQ[1][kc])
                      + (smSQ[2][kc] + smSQ[3][kc]);
            float Pi = g_P[gi * HP + kc];
            float Qi = g_Q[gi * HP + kc];
            float S = 0.55f * ((float)(N - 1) * Pi + sqt - Qi)
                    + 0.45f * (T - fabsf(Pi + Qi));
            #pragma unroll
            for (int o = 0; o < OUTF; o++)
                par[o] += S * W2[kc * OUTF + o];
        }
    }
    #pragma unroll
    for (int off = 16; off > 0; off >>= 1)
        #pragma unroll
        for (int o = 0; o < OUTF; o++)
            par[o] += __shfl_down_sync(0xFFFFFFFFu, par[o], off);

    if (sub == 0) {
        const float* e = inp + gi * 6;
        float* ot = out + gi * 6;
        float p0 = par[0] + (float)(N - 1) * b2[0];
        float p1 = par[1] + (float)(N - 1) * b2[1];
        float p2 = par[2] + (float)(N - 1) * b2[2];
        float p3 = par[3] + (float)(N - 1) * b2[3];
        float p4 = par[4] + (float)(N - 1) * b2[4];
        float p5 = par[5] + (float)(N - 1) * b2[5];
        ot[0] = e[0] + 0.1f * p0;
        ot[1] = e[1] + 0.1f * p1;
        ot[2] = e[2] + 0.1f * p2;
        ot[3] = e[3] + 0.1f * p3;
        ot[4] = 0.1f * softplus_f(p4);
        ot[5] = 0.1f * softplus_f(p5);
    }
}

// ---------------------------------------------------------------------------
extern "C" void kernel_launch(void* const* d_in, const int* in_sizes, int n_in,
                              void* d_out, int out_size)
{
    const float* inp = (const float*)d_in[0];
    const float* W1  = (const float*)d_in[1];
    const float* b1  = (const float*)d_in[2];
    const float* W2  = (const float*)d_in[3];
    const float* b2  = (const float*)d_in[4];
    float* out = (float*)d_out;

    k1_build_PQ<<<B * N / 16, 128>>>(inp, W1, b1);
    k2_fused<<<B * (N / IT), 512>>>(inp, W2, b2, out);
}

// round 6
// speedup vs baseline: 2.7929x; 1.0537x over previous
#include <cuda_runtime.h>
#include <math.h>

#define B 4
#define N 512
#define HID 100
#define HP 128
#define OUTF 6
#define IT 16            // receivers per K2 block
#define JG 4             // j-groups per block
#define UJ 8             // j prefetch depth (per half of ping-pong)

// Scratch (static device; no allocation anywhere)
__device__ float g_P[B * N * HP];
__device__ float g_Q[B * N * HP];

__device__ __forceinline__ float softplus_f(float v)
{
    return fmaxf(v, 0.f) + log1pf(expf(-fabsf(v)));
}

// t = qv*1.0 + p  as FFMA with immediate multiplier (rt_SMSP=1 vs FADD's 2)
__device__ __forceinline__ float fma1(float q, float p)
{
    float r;
    asm("fma.rn.f32 %0, %1, 0f3F800000, %2;" : "=f"(r) : "f"(q), "f"(p));
    return r;
}

// ---------------------------------------------------------------------------
// K1: build P', Q for all (b,n,k).  Block = 128 k-lanes x 16 (b,n) rows.
// ---------------------------------------------------------------------------
__global__ __launch_bounds__(128) void k1_build_PQ(
    const float* __restrict__ inp, const float* __restrict__ W1,
    const float* __restrict__ b1)
{
    int bn0 = blockIdx.x * 16;
    int k   = threadIdx.x;

    __shared__ float rows[16][6];
    if (threadIdx.x < 96) {
        int r = threadIdx.x / 6, c = threadIdx.x % 6;
        rows[r][c] = inp[(bn0 + r) * 6 + c];
    }
    __syncthreads();

    float w0=0,w1=0,w2=0,w3=0,w4=0,w5=0,w6=0,w7=0,w8=0,w9=0,bk=0;
    if (k < HID) {
        w0 = W1[0*HID+k]; w1 = W1[1*HID+k]; w2 = W1[2*HID+k]; w3 = W1[3*HID+k];
        w4 = W1[4*HID+k]; w5 = W1[5*HID+k]; w6 = W1[6*HID+k]; w7 = W1[7*HID+k];
        w8 = W1[8*HID+k]; w9 = W1[9*HID+k]; bk = b1[k];
    }

    #pragma unroll
    for (int r = 0; r < 16; r++) {
        float y = rows[r][0], x = rows[r][1], tau = rows[r][2];
        float sig = rows[r][3], c = rows[r][4], d = rows[r][5];
        float P = 0.f, Q = 0.f;
        if (k < HID) {
            P = tau*w0 + sig*w1 + c*w2 + d*w3 + y*w8 + x*w9 + bk;
            Q = tau*w4 + sig*w5 + c*w6 + d*w7 - y*w8 - x*w9;
        }
        g_P[(bn0 + r) * HP + k] = P;
        g_Q[(bn0 + r) * HP + k] = Q;
    }
}

// ---------------------------------------------------------------------------
// K2: fused O(N^2) abs-sum + sumQ + epilogue.
// Block = 512 thr = 4 j-groups x 128 k-lanes; IT=16 receivers; grid=128.
// j-loop is ping-pong double-buffered: strip B's loads issue before strip A's
// compute, so L2 latency (~250cy) hides under ~800 pipe-cycles of math.
// ---------------------------------------------------------------------------
__global__ __launch_bounds__(512) void k2_fused(
    const float* __restrict__ inp, const float* __restrict__ W2,
    const float* __restrict__ b2, float* __restrict__ out)
{
    int b   = blockIdx.x >> 5;               // 32 tiles per batch
    int i0  = (blockIdx.x & 31) * IT;
    int tid = threadIdx.x;
    int jg  = tid >> 7;                      // 0..3
    int k   = tid & (HP - 1);                // 0..127

    const float* Pp = g_P + (b * N + i0) * HP + k;
    float p[IT];
    #pragma unroll
    for (int ii = 0; ii < IT; ii++) p[ii] = Pp[ii * HP];

    float acc[IT];
    #pragma unroll
    for (int ii = 0; ii < IT; ii++) acc[ii] = 0.f;
    float sq = 0.f;

    const int NJ = N / JG;                   // 128
    const float* q = g_Q + (b * N + jg * NJ) * HP + k;

    float qa[UJ], qb[UJ];
    #pragma unroll
    for (int u = 0; u < UJ; u++) qa[u] = q[u * HP];

    #pragma unroll 1
    for (int j0 = 0; j0 < NJ; j0 += 2 * UJ) {
        // prefetch strip B while computing strip A
        #pragma unroll
        for (int u = 0; u < UJ; u++) qb[u] = q[(j0 + UJ + u) * HP];

        #pragma unroll
        for (int u = 0; u < UJ; u++) {
            float qv = qa[u];
            sq += qv;
            #pragma unroll
            for (int ii = 0; ii < IT; ii++)
                acc[ii] += fabsf(fma1(qv, p[ii]));
        }

        // prefetch next strip A (predicated on uniform guard; no OOB)
        bool more = (j0 + 2 * UJ) < NJ;
        #pragma unroll
        for (int u = 0; u < UJ; u++)
            if (more) qa[u] = q[(j0 + 2 * UJ + u) * HP];

        #pragma unroll
        for (int u = 0; u < UJ; u++) {
            float qv = qb[u];
            sq += qv;
            #pragma unroll
            for (int ii = 0; ii < IT; ii++)
                acc[ii] += fabsf(fma1(qv, p[ii]));
        }
    }

    __shared__ float smT[JG][IT][HP];
    __shared__ float smSQ[JG][HP];
    #pragma unroll
    for (int ii = 0; ii < IT; ii++) smT[jg][ii][k] = acc[ii];
    smSQ[jg][k] = sq;
    __syncthreads();

    // epilogue: warp w handles receiver i=w; lane sub owns k = sub + 32*kk
    int i   = tid >> 5;                      // 0..15
    int sub = tid & 31;
    int gi  = b * N + i0 + i;

    float par[OUTF];
    #pragma unroll
    for (int o = 0; o < OUTF; o++) par[o] = 0.f;

    #pragma unroll
    for (int kk = 0; kk < 4; kk++) {
        int kc = sub + 32 * kk;
        if (kc < HID) {
            float T = (smT[0][i][kc] + smT[1][i][kc])
                    + (smT[2][i][kc] + smT[3][i][kc]);
            float sqt = (smSQ[0][kc] + smSQ[1][kc])
                      + (smSQ[2][kc] + smSQ[3][kc]);
            float Pi = g_P[gi * HP + kc];
            float Qi = g_Q[gi * HP + kc];
            float S = 0.55f * ((float)(N - 1) * Pi + sqt - Qi)
                    + 0.45f * (T - fabsf(Pi + Qi));
            #pragma unroll
            for (int o = 0; o < OUTF; o++)
                par[o] += S * W2[kc * OUTF + o];
        }
    }
    #pragma unroll
    for (int off = 16; off > 0; off >>= 1)
        #pragma unroll
        for (int o = 0; o < OUTF; o++)
            par[o] += __shfl_down_sync(0xFFFFFFFFu, par[o], off);

    if (sub == 0) {
        const float* e = inp + gi * 6;
        float* ot = out + gi * 6;
        float p0 = par[0] + (float)(N - 1) * b2[0];
        float p1 = par[1] + (float)(N - 1) * b2[1];
        float p2 = par[2] + (float)(N - 1) * b2[2];
        float p3 = par[3] + (float)(N - 1) * b2[3];
        float p4 = par[4] + (float)(N - 1) * b2[4];
        float p5 = par[5] + (float)(N - 1) * b2[5];
        ot[0] = e[0] + 0.1f * p0;
        ot[1] = e[1] + 0.1f * p1;
        ot[2] = e[2] + 0.1f * p2;
        ot[3] = e[3] + 0.1f * p3;
        ot[4] = 0.1f * softplus_f(p4);
        ot[5] = 0.1f * softplus_f(p5);
    }
}

// ---------------------------------------------------------------------------
extern "C" void kernel_launch(void* const* d_in, const int* in_sizes, int n_in,
                              void* d_out, int out_size)
{
    const float* inp = (const float*)d_in[0];
    const float* W1  = (const float*)d_in[1];
    const float* b1  = (const float*)d_in[2];
    const float* W2  = (const float*)d_in[3];
    const float* b2  = (const float*)d_in[4];
    float* out = (float*)d_out;

    k1_build_PQ<<<B * N / 16, 128>>>(inp, W1, b1);
    k2_fused<<<B * (N / IT), 512>>>(inp, W2, b2, out);
}

// round 7
// speedup vs baseline: 2.8409x; 1.0172x over previous
#include <cuda_runtime.h>
#include <math.h>

#define B 4
#define N 512
#define HID 100
#define HP 128
#define OUTF 6
#define IT 16            // receivers per K2 block
#define JG 4             // j-groups per block
#define UJ 8             // j prefetch depth (per half of ping-pong)

// Scratch (static device; no allocation anywhere)
__device__ float g_P[B * N * HP];
__device__ float g_Q[B * N * HP];

__device__ __forceinline__ float softplus_f(float v)
{
    return fmaxf(v, 0.f) + log1pf(expf(-fabsf(v)));
}

// t = q*1.0 + p  as FFMA with immediate multiplier (rt_SMSP=1 vs FADD's 2)
__device__ __forceinline__ float fma1(float q, float p)
{
    float r;
    asm("fma.rn.f32 %0, %1, 0f3F800000, %2;" : "=f"(r) : "f"(q), "f"(p));
    return r;
}

// acc = |t|*1.0 + acc ; ptxas folds abs.f32 into the FFMA source modifier,
// keeping the rt=1 imm-form:  FFMA Racc, |Rt|, 1.0, Racc
__device__ __forceinline__ float absfma(float t, float acc)
{
    float r;
    asm("fma.rn.f32 %0, %1, 0f3F800000, %2;" : "=f"(r) : "f"(fabsf(t)), "f"(acc));
    return r;
}

// ---------------------------------------------------------------------------
// K1: build P', Q for all (b,n,k).  Block = 128 k-lanes x 16 (b,n) rows.
// ---------------------------------------------------------------------------
__global__ __launch_bounds__(128) void k1_build_PQ(
    const float* __restrict__ inp, const float* __restrict__ W1,
    const float* __restrict__ b1)
{
    int bn0 = blockIdx.x * 16;
    int k   = threadIdx.x;

    __shared__ float rows[16][6];
    if (threadIdx.x < 96) {
        int r = threadIdx.x / 6, c = threadIdx.x % 6;
        rows[r][c] = inp[(bn0 + r) * 6 + c];
    }
    __syncthreads();

    float w0=0,w1=0,w2=0,w3=0,w4=0,w5=0,w6=0,w7=0,w8=0,w9=0,bk=0;
    if (k < HID) {
        w0 = W1[0*HID+k]; w1 = W1[1*HID+k]; w2 = W1[2*HID+k]; w3 = W1[3*HID+k];
        w4 = W1[4*HID+k]; w5 = W1[5*HID+k]; w6 = W1[6*HID+k]; w7 = W1[7*HID+k];
        w8 = W1[8*HID+k]; w9 = W1[9*HID+k]; bk = b1[k];
    }

    #pragma unroll
    for (int r = 0; r < 16; r++) {
        float y = rows[r][0], x = rows[r][1], tau = rows[r][2];
        float sig = rows[r][3], c = rows[r][4], d = rows[r][5];
        float P = 0.f, Q = 0.f;
        if (k < HID) {
            P = tau*w0 + sig*w1 + c*w2 + d*w3 + y*w8 + x*w9 + bk;
            Q = tau*w4 + sig*w5 + c*w6 + d*w7 - y*w8 - x*w9;
        }
        g_P[(bn0 + r) * HP + k] = P;
        g_Q[(bn0 + r) * HP + k] = Q;
    }
}

// ---------------------------------------------------------------------------
// K2: fused O(N^2) abs-sum + sumQ + epilogue.
// Block = 512 thr = 4 j-groups x 128 k-lanes; IT=16 receivers; grid=128.
// Ping-pong double-buffered j loads; inner pair = 2x FFMA-imm (rt=1 each):
//   t = q*1+p ;  acc = |t|*1+acc
// ---------------------------------------------------------------------------
__global__ __launch_bounds__(512) void k2_fused(
    const float* __restrict__ inp, const float* __restrict__ W2,
    const float* __restrict__ b2, float* __restrict__ out)
{
    int b   = blockIdx.x >> 5;               // 32 tiles per batch
    int i0  = (blockIdx.x & 31) * IT;
    int tid = threadIdx.x;
    int jg  = tid >> 7;                      // 0..3
    int k   = tid & (HP - 1);                // 0..127

    const float* Pp = g_P + (b * N + i0) * HP + k;
    float p[IT];
    #pragma unroll
    for (int ii = 0; ii < IT; ii++) p[ii] = Pp[ii * HP];

    float acc[IT];
    #pragma unroll
    for (int ii = 0; ii < IT; ii++) acc[ii] = 0.f;
    float sq = 0.f;

    const int NJ = N / JG;                   // 128
    const float* q = g_Q + (b * N + jg * NJ) * HP + k;

    float qa[UJ], qb[UJ];
    #pragma unroll
    for (int u = 0; u < UJ; u++) qa[u] = q[u * HP];

    #pragma unroll 1
    for (int j0 = 0; j0 < NJ; j0 += 2 * UJ) {
        // prefetch strip B while computing strip A
        #pragma unroll
        for (int u = 0; u < UJ; u++) qb[u] = q[(j0 + UJ + u) * HP];

        #pragma unroll
        for (int u = 0; u < UJ; u++) {
            float qv = qa[u];
            sq = fma1(qv, sq);
            #pragma unroll
            for (int ii = 0; ii < IT; ii++)
                acc[ii] = absfma(fma1(qv, p[ii]), acc[ii]);
        }

        // prefetch next strip A (predicated on uniform guard; no OOB)
        bool more = (j0 + 2 * UJ) < NJ;
        #pragma unroll
        for (int u = 0; u < UJ; u++)
            if (more) qa[u] = q[(j0 + 2 * UJ + u) * HP];

        #pragma unroll
        for (int u = 0; u < UJ; u++) {
            float qv = qb[u];
            sq = fma1(qv, sq);
            #pragma unroll
            for (int ii = 0; ii < IT; ii++)
                acc[ii] = absfma(fma1(qv, p[ii]), acc[ii]);
        }
    }

    __shared__ float smT[JG][IT][HP];
    __shared__ float smSQ[JG][HP];
    #pragma unroll
    for (int ii = 0; ii < IT; ii++) smT[jg][ii][k] = acc[ii];
    smSQ[jg][k] = sq;
    __syncthreads();

    // epilogue: warp w handles receiver i=w; lane sub owns k = sub + 32*kk
    int i   = tid >> 5;                      // 0..15
    int sub = tid & 31;
    int gi  = b * N + i0 + i;

    float par[OUTF];
    #pragma unroll
    for (int o = 0; o < OUTF; o++) par[o] = 0.f;

    #pragma unroll
    for (int kk = 0; kk < 4; kk++) {
        int kc = sub + 32 * kk;
        if (kc < HID) {
            float T = (smT[0][i][kc] + smT[1][i][kc])
                    + (smT[2][i][kc] + smT[3][i][kc]);
            float sqt = (smSQ[0][kc] + smSQ[1][kc])
                      + (smSQ[2][kc] + smSQ[3][kc]);
            float Pi = g_P[gi * HP + kc];
            float Qi = g_Q[gi * HP + kc];
            float S = 0.55f * ((float)(N - 1) * Pi + sqt - Qi)
                    + 0.45f * (T - fabsf(Pi + Qi));
            #pragma unroll
            for (int o = 0; o < OUTF; o++)
                par[o] += S * W2[kc * OUTF + o];
        }
    }
    #pragma unroll
    for (int off = 16; off > 0; off >>= 1)
        #pragma unroll
        for (int o = 0; o < OUTF; o++)
            par[o] += __shfl_down_sync(0xFFFFFFFFu, par[o], off);

    if (sub == 0) {
        const float* e = inp + gi * 6;
        float* ot = out + gi * 6;
        float p0 = par[0] + (float)(N - 1) * b2[0];
        float p1 = par[1] + (float)(N - 1) * b2[1];
        float p2 = par[2] + (float)(N - 1) * b2[2];
        float p3 = par[3] + (float)(N - 1) * b2[3];
        float p4 = par[4] + (float)(N - 1) * b2[4];
        float p5 = par[5] + (float)(N - 1) * b2[5];
        ot[0] = e[0] + 0.1f * p0;
        ot[1] = e[1] + 0.1f * p1;
        ot[2] = e[2] + 0.1f * p2;
        ot[3] = e[3] + 0.1f * p3;
        ot[4] = 0.1f * softplus_f(p4);
        ot[5] = 0.1f * softplus_f(p5);
    }
}

// ---------------------------------------------------------------------------
extern "C" void kernel_launch(void* const* d_in, const int* in_sizes, int n_in,
                              void* d_out, int out_size)
{
    const float* inp = (const float*)d_in[0];
    const float* W1  = (const float*)d_in[1];
    const float* b1  = (const float*)d_in[2];
    const float* W2  = (const float*)d_in[3];
    const float* b2  = (const float*)d_in[4];
    float* out = (float*)d_out;

    k1_build_PQ<<<B * N / 16, 128>>>(inp, W1, b1);
    k2_fused<<<B * (N / IT), 512>>>(inp, W2, b2, out);
}